// round 7
// baseline (speedup 1.0000x reference)
#include <cuda_runtime.h>
#include <cuda_fp16.h>
#include <math.h>
#include <stdint.h>

// ---------------------------------------------------------------------------
// Shapes: sparse_fea[64,256,64] dense_fea[64,128,4096] stk_coor[64,64,32]
//         conv_w[256,128,3] (flat [256][384]) bn_gamma/beta[256]
// Output: sparse_out[64,256,32] | dense_out[64,256,1024] | coor[64,32,32]
// ---------------------------------------------------------------------------

#define OFF_DENSE 524288
#define OFF_COOR  (524288 + 16777216)

__device__ int      g_fps_idx[64 * 32];
__device__ uint32_t g_yh[64 * 256 * 512];     // conv output scratch (half2)
__device__ float    g_sum[256];
__device__ float    g_sqsum[256];
__device__ uint32_t g_wth[256 * 192];         // fp16 weights [co][chunk16][12 half2]

__device__ __forceinline__ unsigned smem_addr(const void* p) {
    return (unsigned)__cvta_generic_to_shared(p);
}
__device__ __forceinline__ void cp_async16(unsigned dst, const void* src) {
    asm volatile("cp.async.cg.shared.global [%0], [%1], 16;\n" :: "r"(dst), "l"(src));
}
__device__ __forceinline__ float tanh_fast(float x) {
    float r;
    asm("tanh.approx.f32 %0, %1;" : "=f"(r) : "f"(x));
    return r;
}
__device__ __forceinline__ void mma16(float c[4], const uint32_t a[4],
                                      uint32_t b0, uint32_t b1) {
    asm volatile(
        "mma.sync.aligned.m16n8k16.row.col.f32.f16.f16.f32 "
        "{%0,%1,%2,%3},{%4,%5,%6,%7},{%8,%9},{%0,%1,%2,%3};"
        : "+f"(c[0]), "+f"(c[1]), "+f"(c[2]), "+f"(c[3])
        : "r"(a[0]), "r"(a[1]), "r"(a[2]), "r"(a[3]), "r"(b0), "r"(b1));
}
__device__ __forceinline__ void mma8(float c[4], uint32_t a0, uint32_t a1,
                                     uint32_t b0) {
    asm volatile(
        "mma.sync.aligned.m16n8k8.row.col.f32.f16.f16.f32 "
        "{%0,%1,%2,%3},{%4,%5},{%6},{%0,%1,%2,%3};"
        : "+f"(c[0]), "+f"(c[1]), "+f"(c[2]), "+f"(c[3])
        : "r"(a0), "r"(a1), "r"(b0));
}
__device__ __forceinline__ uint32_t pack_h2(float lo, float hi) {
    __half2 h = __floats2half2_rn(lo, hi);      // .x = lo (low 16 bits)
    return *(uint32_t*)&h;
}

// ---------------------------------------------------------------------------
// Weight prep: fp16, ordering [co][chunk c][k24], k = cl_local*3 + tap,
// packed as 12 half2 words per (co, chunk).
// ---------------------------------------------------------------------------
__global__ void wprep_kernel(const float* __restrict__ w)
{
    int co = blockIdx.x;                 // 256
    int t  = threadIdx.x;                // 0..191
    int c  = t / 12;
    int j  = t - c * 12;                 // half2 index
    int k0 = 2 * j, k1 = 2 * j + 1;
    int cin0 = c * 8 + k0 / 3, tap0 = k0 % 3;
    int cin1 = c * 8 + k1 / 3, tap1 = k1 % 3;
    float f0 = w[co * 384 + cin0 * 3 + tap0];
    float f1 = w[co * 384 + cin1 * 3 + tap1];
    g_wth[co * 192 + c * 12 + j] = pack_h2(f0, f1);
}

// ---------------------------------------------------------------------------
// FPS: one block per batch, 64 threads. Block 0 zeroes BN accumulators.
// ---------------------------------------------------------------------------
__global__ void fps_kernel(const float* __restrict__ stk_coor,
                           float* __restrict__ out_coor)
{
    int b = blockIdx.x;
    int t = threadIdx.x;                     // 0..63

    if (b == 0) {
        for (int i = t; i < 256; i += 64) { g_sum[i] = 0.f; g_sqsum[i] = 0.f; }
    }

    __shared__ float coor[64][33];
    __shared__ float sdist[64];
    __shared__ int   sidx[32];
    __shared__ int   s_far;

    #pragma unroll
    for (int c = 0; c < 32; c++)
        coor[t][c] = stk_coor[(b * 64 + t) * 32 + c];
    if (t == 0) s_far = 0;
    float dist = 1e10f;
    __syncthreads();

    for (int i = 0; i < 32; i++) {
        int far = s_far;
        if (t == 0) sidx[i] = far;
        float d = 0.f;
        #pragma unroll
        for (int c = 0; c < 32; c++) {
            float df = coor[t][c] - coor[far][c];
            d += df * df;
        }
        dist = fminf(dist, d);
        sdist[t] = dist;
        __syncthreads();
        if (t < 32) {
            float bv = sdist[t];       int bi = t;
            float v2 = sdist[t + 32];
            if (v2 > bv) { bv = v2; bi = t + 32; }
            #pragma unroll
            for (int off = 16; off > 0; off >>= 1) {
                float ov = __shfl_down_sync(0xffffffffu, bv, off);
                int   oi = __shfl_down_sync(0xffffffffu, bi, off);
                if (ov > bv || (ov == bv && oi < bi)) { bv = ov; bi = oi; }
            }
            if (t == 0) s_far = bi;
        }
        __syncthreads();
    }

    if (t < 32) g_fps_idx[b * 32 + t] = sidx[t];
    for (int v = t; v < 32 * 32; v += 64) {
        int i = v >> 5, c = v & 31;
        out_coor[(b * 32 + i) * 32 + c] = coor[sidx[i]][c];
    }
}

// ---------------------------------------------------------------------------
// sparse_out[b,e,s] = sparse_fea[b,e,idx[b,s]]
// ---------------------------------------------------------------------------
__global__ void gather_sparse(const float* __restrict__ sp,
                              float* __restrict__ out)
{
    int t = blockIdx.x * 256 + threadIdx.x;     // < 524288
    int b = t >> 13;
    int r = t & 8191;
    int e = r >> 5;
    int s = r & 31;
    out[t] = sp[(size_t)(b * 256 + e) * 64 + g_fps_idx[b * 32 + s]];
}

// ---------------------------------------------------------------------------
// fp16 conv-as-GEMM, fully double-buffered: ONE barrier per K-chunk.
// 512 threads, tile M=128 co x N=256 (8 strokes x 32 q), K=384 in 16x24.
// smem word offsets:
//   WB0 0,     WB1 2560   : fp16 weights [128 co][20 words, 12 used]
//   BB0 5120,  BB1 10240  : im2col B [256 n][20 words, 12 used]
//   RAW0 15360, RAW1 19968: raw x rows [64][72], x[p] at word p+4, 0 at word 3
// Chunk c: LDG(c+1) -> STS_RAW(c+1,^) -> bar -> BUILD_B(c+1,^) ; MMA(c)
// Epilogue reuses smem as ys[64][268]; y stored to gmem as half2.
// ---------------------------------------------------------------------------
#define WB1  2560
#define BB0  5120
#define BB1  10240
#define RAW0 15360
#define RAW1 19968
#define CONV_SMEM 98304

__global__ void __launch_bounds__(512, 1)
conv_mma_kernel(const float* __restrict__ dense)
{
    extern __shared__ float smem[];
    uint32_t* smem_u = (uint32_t*)smem;

    const int b    = blockIdx.y;
    const int ch   = blockIdx.x & 1;       // co half
    const int sgrp = blockIdx.x >> 1;      // 0..3
    const int co0  = ch * 128;
    const int t    = threadIdx.x;
    const int wp   = t >> 5;               // 0..15
    const int lane = t & 31;
    const int g    = lane >> 2;
    const int tig  = lane & 3;
    const int wm   = wp & 3;
    const int wn   = wp >> 2;
    const int m_warp = wm * 32;
    const int n_warp = wn * 64;

    __shared__ int stk[8];
    if (t < 8) stk[t] = g_fps_idx[b * 32 + sgrp * 8 + t];
    if (t < 128) {                         // zero p=-1 pads in BOTH raw buffers
        int bi = t >> 6, r = t & 63;
        smem[(bi ? RAW1 : RAW0) + r * 72 + 3] = 0.f;
    }
    __syncthreads();

    float4 xr[2];

    #define LDG_X(cc)                                                        \
        _Pragma("unroll")                                                    \
        for (int i = 0; i < 2; i++) {                                        \
            int v = t + 512 * i;                                             \
            int row = v >> 4, j = v & 15;                                    \
            int cl = row >> 3, s = row & 7;                                  \
            xr[i] = *(const float4*)&dense[(size_t)(b * 128 + (cc) * 8 + cl) \
                                           * 4096 + (size_t)stk[s] * 64 + j * 4]; \
        }

    #define STS_RAW(rbuf)                                                    \
        _Pragma("unroll")                                                    \
        for (int i = 0; i < 2; i++) {                                        \
            int v = t + 512 * i;                                             \
            int row = v >> 4, j = v & 15;                                    \
            *(float4*)&smem[((rbuf) ? RAW1 : RAW0) + row * 72 + 4 + 4 * j] = xr[i]; \
        }

    #define STAGE_W(cc, buf)                                                 \
        if (t < 384) {                                                       \
            int co = t / 3, seg = t - co * 3;                                \
            cp_async16(smem_addr(smem_u + (buf) * WB1 + co * 20 + seg * 4),  \
                       g_wth + (size_t)(co0 + co) * 192 + (cc) * 12 + seg * 4); \
        }

    // im2col build: thread covers n = t&255, k-half h2 = t>>8 (6 half2 each)
    #define BUILD_B(bbuf)                                                    \
        {                                                                    \
            int n  = t & 255;                                                \
            int h2 = t >> 8;                                                 \
            int s  = n >> 5, q = n & 31;                                     \
            const float* rbase = smem + ((bbuf) ? RAW1 : RAW0);              \
            float f[12];                                                     \
            _Pragma("unroll")                                                \
            for (int cr = 0; cr < 4; cr++) {                                 \
                const float* rrow = rbase + (h2 * 4 + cr) * 576 +            \
                                    s * 72 + 2 * q;                          \
                float2 u0 = *(const float2*)(rrow + 2);                      \
                float2 u1 = *(const float2*)(rrow + 4);                      \
                f[cr * 3 + 0] = u0.y;                                        \
                f[cr * 3 + 1] = u1.x;                                        \
                f[cr * 3 + 2] = u1.y;                                        \
            }                                                                \
            uint32_t* dst = smem_u + ((bbuf) ? BB1 : BB0) + n * 20 + h2 * 6; \
            ((uint2*)dst)[0] = make_uint2(pack_h2(f[0], f[1]),               \
                                          pack_h2(f[2], f[3]));              \
            ((uint2*)(dst + 2))[0] = make_uint2(pack_h2(f[4], f[5]),         \
                                                pack_h2(f[6], f[7]));        \
            ((uint2*)(dst + 4))[0] = make_uint2(pack_h2(f[8], f[9]),         \
                                                pack_h2(f[10], f[11]));      \
        }

    // prologue: chunk 0 -> buffers 0
    LDG_X(0);
    STAGE_W(0, 0);
    asm volatile("cp.async.commit_group;");
    STS_RAW(0);
    asm volatile("cp.async.wait_group 0;");
    __syncthreads();
    BUILD_B(0);
    __syncthreads();                       // BB0 published

    // fragment base offsets (word units)
    const int abase = m_warp * 20 + g * 20 + tig;          // + buf*WB1
    const int bidx  = (n_warp + g) * 20 + tig;             // + BBx + nf*160

    float acc[2][8][4];
    #pragma unroll
    for (int mf = 0; mf < 2; mf++)
        #pragma unroll
        for (int nf = 0; nf < 8; nf++)
            #pragma unroll
            for (int i = 0; i < 4; i++) acc[mf][nf][i] = 0.f;

    for (int c = 0; c < 16; ++c) {
        int pb = c & 1;
        if (c + 1 < 16) {
            LDG_X(c + 1);
            STAGE_W(c + 1, pb ^ 1);
            asm volatile("cp.async.commit_group;");
            STS_RAW(pb ^ 1);
            asm volatile("cp.async.wait_group 0;");
            __syncthreads();               // RAW(c+1) published; BUILD_B(c)
                                           // from all warps retired
            BUILD_B(pb ^ 1);               // overlaps with MMA(c) below (ILP)
        } else {
            __syncthreads();               // ensure BUILD_B(15) from all warps
        }

        const uint32_t* aw = smem_u + pb * WB1 + abase;
        const uint32_t* bw = smem_u + (pb ? BB1 : BB0) + bidx;

        // k16 step (k_local 0..15)
        {
            uint32_t A[2][4];
            #pragma unroll
            for (int mf = 0; mf < 2; mf++) {
                A[mf][0] = aw[mf * 320];
                A[mf][1] = aw[mf * 320 + 160];
                A[mf][2] = aw[mf * 320 + 4];
                A[mf][3] = aw[mf * 320 + 164];
            }
            #pragma unroll
            for (int nf = 0; nf < 8; nf++) {
                uint32_t B0 = bw[nf * 160];
                uint32_t B1 = bw[nf * 160 + 4];
                mma16(acc[0][nf], A[0], B0, B1);
                mma16(acc[1][nf], A[1], B0, B1);
            }
        }
        // k8 step (k_local 16..23)
        {
            uint32_t A0a = aw[8],       A0b = aw[168];
            uint32_t A1a = aw[320 + 8], A1b = aw[320 + 168];
            #pragma unroll
            for (int nf = 0; nf < 8; nf++) {
                uint32_t B0 = bw[nf * 160 + 8];
                mma8(acc[0][nf], A0a, A0b, B0);
                mma8(acc[1][nf], A1a, A1b, B0);
            }
        }
    }

    // --- fused BN partial sums
    #pragma unroll
    for (int mf = 0; mf < 2; mf++) {
        float s0 = 0.f, q0 = 0.f, s1 = 0.f, q1 = 0.f;
        #pragma unroll
        for (int nf = 0; nf < 8; nf++) {
            float c0 = acc[mf][nf][0], c1 = acc[mf][nf][1];
            float c2 = acc[mf][nf][2], c3 = acc[mf][nf][3];
            s0 += c0 + c1;  q0 += c0 * c0 + c1 * c1;
            s1 += c2 + c3;  q1 += c2 * c2 + c3 * c3;
        }
        #pragma unroll
        for (int off = 1; off < 4; off <<= 1) {
            s0 += __shfl_xor_sync(0xffffffffu, s0, off);
            q0 += __shfl_xor_sync(0xffffffffu, q0, off);
            s1 += __shfl_xor_sync(0xffffffffu, s1, off);
            q1 += __shfl_xor_sync(0xffffffffu, q1, off);
        }
        if (tig == 0) {
            int co = co0 + m_warp + mf * 16 + g;
            atomicAdd(&g_sum[co],       s0);
            atomicAdd(&g_sqsum[co],     q0);
            atomicAdd(&g_sum[co + 8],   s1);
            atomicAdd(&g_sqsum[co + 8], q1);
        }
    }

    // --- epilogue: two-phase smem transpose, pack to half2, coalesced STG
    float* ys = smem;                      // [64][268]
    #pragma unroll
    for (int ph = 0; ph < 2; ph++) {
        __syncthreads();
        if ((wm >> 1) == ph) {
            #pragma unroll
            for (int mf = 0; mf < 2; mf++)
                #pragma unroll
                for (int nf = 0; nf < 8; nf++) {
                    int row = (wm & 1) * 32 + mf * 16 + g;
                    int nC  = n_warp + nf * 8 + 2 * tig;
                    *(float2*)&ys[row * 268 + nC] =
                        make_float2(acc[mf][nf][0], acc[mf][nf][1]);
                    *(float2*)&ys[(row + 8) * 268 + nC] =
                        make_float2(acc[mf][nf][2], acc[mf][nf][3]);
                }
        }
        __syncthreads();
        int row = t >> 3, jb = t & 7;
        uint32_t* dst = g_yh + ((size_t)(b * 256 + co0 + ph * 64 + row)) * 512 +
                        sgrp * 128;
        #pragma unroll
        for (int jj = 0; jj < 8; jj++) {
            int j = jb + jj * 8;
            float4 v = *(const float4*)&ys[row * 268 + j * 4];
            *(uint2*)&dst[j * 2] = make_uint2(pack_h2(v.x, v.y),
                                              pack_h2(v.z, v.w));
        }
    }
}

// ---------------------------------------------------------------------------
// Normalize + scale/shift + tanh-GELU from half2 scratch; stats inline.
// One thread = 8 values (uint4 of half2).
// ---------------------------------------------------------------------------
__global__ void bn_gelu_kernel(const float* __restrict__ gamma,
                               const float* __restrict__ beta,
                               float* __restrict__ out)
{
    int i = blockIdx.x * 256 + threadIdx.x;    // < 2097152 (uint4 index)
    int co = (i >> 7) & 255;                   // 128 uint4 per (b,co) row
    float mean = g_sum[co] * (1.f / 65536.f);
    float var  = g_sqsum[co] * (1.f / 65536.f) - mean * mean;
    float ga = rsqrtf(var + 1e-5f) * gamma[co];
    float be = beta[co];

    uint4 v = ((const uint4*)g_yh)[i];
    float vals[8];
    {
        float2 f0 = __half22float2(*(__half2*)&v.x);
        float2 f1 = __half22float2(*(__half2*)&v.y);
        float2 f2 = __half22float2(*(__half2*)&v.z);
        float2 f3 = __half22float2(*(__half2*)&v.w);
        vals[0] = f0.x; vals[1] = f0.y; vals[2] = f1.x; vals[3] = f1.y;
        vals[4] = f2.x; vals[5] = f2.y; vals[6] = f3.x; vals[7] = f3.y;
    }
    float r[8];
    #pragma unroll
    for (int j = 0; j < 8; j++) {
        float x = (vals[j] - mean) * ga + be;
        float u = 0.7978845608028654f * (x + 0.044715f * x * x * x);
        r[j] = 0.5f * x * (1.f + tanh_fast(u));
    }
    float4* o = (float4*)&out[(size_t)i * 8];
    o[0] = make_float4(r[0], r[1], r[2], r[3]);
    o[1] = make_float4(r[4], r[5], r[6], r[7]);
}

// ---------------------------------------------------------------------------
extern "C" void kernel_launch(void* const* d_in, const int* in_sizes, int n_in,
                              void* d_out, int out_size)
{
    const float* sparse_fea = (const float*)d_in[0];
    const float* dense_fea  = (const float*)d_in[1];
    const float* stk_coor   = (const float*)d_in[2];
    const float* conv_w     = (const float*)d_in[3];
    // d_in[4] = conv_b: zeros AND cancels under batch-stat BN.
    const float* bn_gamma   = (const float*)d_in[5];
    const float* bn_beta    = (const float*)d_in[6];
    float* out = (float*)d_out;

    cudaFuncSetAttribute(conv_mma_kernel,
                         cudaFuncAttributeMaxDynamicSharedMemorySize, CONV_SMEM);

    wprep_kernel<<<256, 192>>>(conv_w);
    fps_kernel<<<64, 64>>>(stk_coor, out + OFF_COOR);
    gather_sparse<<<2048, 256>>>(sparse_fea, out);
    conv_mma_kernel<<<dim3(8, 64), 512, CONV_SMEM>>>(dense_fea);
    bn_gelu_kernel<<<8192, 256>>>(bn_gamma, bn_beta, out + OFF_DENSE);
}

// round 8
// speedup vs baseline: 1.1839x; 1.1839x over previous
#include <cuda_runtime.h>
#include <cuda_fp16.h>
#include <math.h>
#include <stdint.h>

// ---------------------------------------------------------------------------
// Shapes: sparse_fea[64,256,64] dense_fea[64,128,4096] stk_coor[64,64,32]
//         conv_w[256,128,3] (flat [256][384]) bn_gamma/beta[256]
// Output: sparse_out[64,256,32] | dense_out[64,256,1024] | coor[64,32,32]
// ---------------------------------------------------------------------------

#define OFF_DENSE 524288
#define OFF_COOR  (524288 + 16777216)

__device__ int      g_fps_idx[64 * 32];
__device__ uint32_t g_yh[64 * 256 * 512];     // conv output scratch (half2)
__device__ float    g_sum[256];
__device__ float    g_sqsum[256];
__device__ uint32_t g_wth[256 * 192];         // fp16 weights [co][chunk16][12 half2]

__device__ __forceinline__ unsigned smem_addr(const void* p) {
    return (unsigned)__cvta_generic_to_shared(p);
}
__device__ __forceinline__ void cp_async16(unsigned dst, const void* src) {
    asm volatile("cp.async.cg.shared.global [%0], [%1], 16;\n" :: "r"(dst), "l"(src));
}
__device__ __forceinline__ float tanh_fast(float x) {
    float r;
    asm("tanh.approx.f32 %0, %1;" : "=f"(r) : "f"(x));
    return r;
}
__device__ __forceinline__ void mma16(float c[4], const uint32_t a[4],
                                      uint32_t b0, uint32_t b1) {
    asm volatile(
        "mma.sync.aligned.m16n8k16.row.col.f32.f16.f16.f32 "
        "{%0,%1,%2,%3},{%4,%5,%6,%7},{%8,%9},{%0,%1,%2,%3};"
        : "+f"(c[0]), "+f"(c[1]), "+f"(c[2]), "+f"(c[3])
        : "r"(a[0]), "r"(a[1]), "r"(a[2]), "r"(a[3]), "r"(b0), "r"(b1));
}
__device__ __forceinline__ void mma8(float c[4], uint32_t a0, uint32_t a1,
                                     uint32_t b0) {
    asm volatile(
        "mma.sync.aligned.m16n8k8.row.col.f32.f16.f16.f32 "
        "{%0,%1,%2,%3},{%4,%5},{%6},{%0,%1,%2,%3};"
        : "+f"(c[0]), "+f"(c[1]), "+f"(c[2]), "+f"(c[3])
        : "r"(a0), "r"(a1), "r"(b0));
}
__device__ __forceinline__ uint32_t pack_h2(float lo, float hi) {
    __half2 h = __floats2half2_rn(lo, hi);      // .x = lo (low 16 bits)
    return *(uint32_t*)&h;
}

// ---------------------------------------------------------------------------
// Weight prep: fp16, ordering [co][chunk c][k24], k = cl_local*3 + tap,
// packed as 12 half2 words per (co, chunk).
// ---------------------------------------------------------------------------
__global__ void wprep_kernel(const float* __restrict__ w)
{
    int co = blockIdx.x;                 // 256
    int t  = threadIdx.x;                // 0..191
    int c  = t / 12;
    int j  = t - c * 12;                 // half2 index
    int k0 = 2 * j, k1 = 2 * j + 1;
    int cin0 = c * 8 + k0 / 3, tap0 = k0 % 3;
    int cin1 = c * 8 + k1 / 3, tap1 = k1 % 3;
    float f0 = w[co * 384 + cin0 * 3 + tap0];
    float f1 = w[co * 384 + cin1 * 3 + tap1];
    g_wth[co * 192 + c * 12 + j] = pack_h2(f0, f1);
}

// ---------------------------------------------------------------------------
// FPS: one block per batch, 64 threads. Block 0 zeroes BN accumulators.
// ---------------------------------------------------------------------------
__global__ void fps_kernel(const float* __restrict__ stk_coor,
                           float* __restrict__ out_coor)
{
    int b = blockIdx.x;
    int t = threadIdx.x;                     // 0..63

    if (b == 0) {
        for (int i = t; i < 256; i += 64) { g_sum[i] = 0.f; g_sqsum[i] = 0.f; }
    }

    __shared__ float coor[64][33];
    __shared__ float sdist[64];
    __shared__ int   sidx[32];
    __shared__ int   s_far;

    #pragma unroll
    for (int c = 0; c < 32; c++)
        coor[t][c] = stk_coor[(b * 64 + t) * 32 + c];
    if (t == 0) s_far = 0;
    float dist = 1e10f;
    __syncthreads();

    for (int i = 0; i < 32; i++) {
        int far = s_far;
        if (t == 0) sidx[i] = far;
        float d = 0.f;
        #pragma unroll
        for (int c = 0; c < 32; c++) {
            float df = coor[t][c] - coor[far][c];
            d += df * df;
        }
        dist = fminf(dist, d);
        sdist[t] = dist;
        __syncthreads();
        if (t < 32) {
            float bv = sdist[t];       int bi = t;
            float v2 = sdist[t + 32];
            if (v2 > bv) { bv = v2; bi = t + 32; }
            #pragma unroll
            for (int off = 16; off > 0; off >>= 1) {
                float ov = __shfl_down_sync(0xffffffffu, bv, off);
                int   oi = __shfl_down_sync(0xffffffffu, bi, off);
                if (ov > bv || (ov == bv && oi < bi)) { bv = ov; bi = oi; }
            }
            if (t == 0) s_far = bi;
        }
        __syncthreads();
    }

    if (t < 32) g_fps_idx[b * 32 + t] = sidx[t];
    for (int v = t; v < 32 * 32; v += 64) {
        int i = v >> 5, c = v & 31;
        out_coor[(b * 32 + i) * 32 + c] = coor[sidx[i]][c];
    }
}

// ---------------------------------------------------------------------------
// sparse_out[b,e,s] = sparse_fea[b,e,idx[b,s]]
// ---------------------------------------------------------------------------
__global__ void gather_sparse(const float* __restrict__ sp,
                              float* __restrict__ out)
{
    int t = blockIdx.x * 256 + threadIdx.x;     // < 524288
    int b = t >> 13;
    int r = t & 8191;
    int e = r >> 5;
    int s = r & 31;
    out[t] = sp[(size_t)(b * 256 + e) * 64 + g_fps_idx[b * 32 + s]];
}

// ---------------------------------------------------------------------------
// fp16 conv-as-GEMM, cp.async 3-deep pipeline, ONE barrier per K-chunk.
// 512 threads, tile M=128 co x N=256 (8 strokes x 32 q), K=384 in 16x24.
// smem word offsets (ring buffers):
//   WB(i)  = i*2560,        i=0..3 : fp16 weights [128 co][20w, 12 used]
//   BB0 10240, BB1 15360           : im2col B [256 n][20w, 12 used]
//   RAW(i) = 20480 + i*4608, i=0..3: raw x rows [64][72], x[p]@p+4, 0@3
// Iter c: wait_group 1; bar; BUILD_B(c+1) || MMA(c); stage(c+3).
// Ring reuse is always separated by >=1 barrier (audited per buffer).
// Epilogue reuses smem as ys[64][268]; y stored to gmem as half2.
// ---------------------------------------------------------------------------
#define BB0  10240
#define BB1  15360
#define RAWB 20480
#define CONV_SMEM 155648

__global__ void __launch_bounds__(512, 1)
conv_mma_kernel(const float* __restrict__ dense)
{
    extern __shared__ float smem[];
    uint32_t* smem_u = (uint32_t*)smem;

    const int b    = blockIdx.y;
    const int ch   = blockIdx.x & 1;       // co half
    const int sgrp = blockIdx.x >> 1;      // 0..3
    const int co0  = ch * 128;
    const int t    = threadIdx.x;
    const int wp   = t >> 5;               // 0..15
    const int lane = t & 31;
    const int g    = lane >> 2;
    const int tig  = lane & 3;
    const int wm   = wp & 3;
    const int wn   = wp >> 2;
    const int m_warp = wm * 32;
    const int n_warp = wn * 64;

    __shared__ int stk[8];
    if (t < 8) stk[t] = g_fps_idx[b * 32 + sgrp * 8 + t];
    if (t < 256) {                         // zero p=-1 pads in all 4 RAW bufs
        int bi = t >> 6, r = t & 63;
        smem[RAWB + bi * 4608 + r * 72 + 3] = 0.f;
    }
    __syncthreads();

    // one commit group per chunk: x rows (cp.async direct to RAW) + weights
    #define STAGE(cc)                                                        \
        {                                                                    \
            int rb = (cc) & 3;                                               \
            _Pragma("unroll")                                                \
            for (int i = 0; i < 2; i++) {                                    \
                int v = t + 512 * i;                                         \
                int row = v >> 4, j = v & 15;                                \
                int cl = row >> 3, s = row & 7;                              \
                cp_async16(smem_addr(smem_u + RAWB + rb * 4608 +             \
                                     row * 72 + 4 + 4 * j),                  \
                           &dense[(size_t)(b * 128 + (cc) * 8 + cl) * 4096 + \
                                  (size_t)stk[s] * 64 + j * 4]);             \
            }                                                                \
            if (t < 384) {                                                   \
                int co = t / 3, seg = t - co * 3;                            \
                cp_async16(smem_addr(smem_u + rb * 2560 + co * 20 + seg * 4),\
                           g_wth + (size_t)(co0 + co) * 192 + (cc) * 12 +    \
                           seg * 4);                                         \
            }                                                                \
            asm volatile("cp.async.commit_group;");                          \
        }

    // im2col build: thread covers n = t&255, k-half h2 = t>>8 (6 half2 each)
    #define BUILD_B(cc)                                                      \
        {                                                                    \
            int n  = t & 255;                                                \
            int h2 = t >> 8;                                                 \
            int s  = n >> 5, q = n & 31;                                     \
            const float* rbase = smem + RAWB + ((cc) & 3) * 4608;            \
            float f[12];                                                     \
            _Pragma("unroll")                                                \
            for (int cr = 0; cr < 4; cr++) {                                 \
                const float* rrow = rbase + (h2 * 4 + cr) * 576 +            \
                                    s * 72 + 2 * q;                          \
                float2 u0 = *(const float2*)(rrow + 2);                      \
                float2 u1 = *(const float2*)(rrow + 4);                      \
                f[cr * 3 + 0] = u0.y;                                        \
                f[cr * 3 + 1] = u1.x;                                        \
                f[cr * 3 + 2] = u1.y;                                        \
            }                                                                \
            uint32_t* dst = smem_u + (((cc) & 1) ? BB1 : BB0) + n * 20 +     \
                            h2 * 6;                                          \
            ((uint2*)dst)[0] = make_uint2(pack_h2(f[0], f[1]),               \
                                          pack_h2(f[2], f[3]));              \
            ((uint2*)(dst + 2))[0] = make_uint2(pack_h2(f[4], f[5]),         \
                                                pack_h2(f[6], f[7]));        \
            ((uint2*)(dst + 4))[0] = make_uint2(pack_h2(f[8], f[9]),         \
                                                pack_h2(f[10], f[11]));      \
        }

    // prologue: fill pipeline with chunks 0,1,2
    STAGE(0);
    STAGE(1);
    STAGE(2);
    asm volatile("cp.async.wait_group 2;");    // chunk 0 arrived
    __syncthreads();
    BUILD_B(0);

    // fragment base offsets (word units)
    const int abase = m_warp * 20 + g * 20 + tig;          // + wbuf*2560
    const int bidx  = (n_warp + g) * 20 + tig;             // + BBx + nf*160

    float acc[2][8][4];
    #pragma unroll
    for (int mf = 0; mf < 2; mf++)
        #pragma unroll
        for (int nf = 0; nf < 8; nf++)
            #pragma unroll
            for (int i = 0; i < 4; i++) acc[mf][nf][i] = 0.f;

    for (int c = 0; c < 16; ++c) {
        asm volatile("cp.async.wait_group 1;");    // chunk c+1 arrived
        __syncthreads();    // publishes BUILD_B(c) + RAW(c+1); retires MMA(c-1)

        if (c + 1 < 16) BUILD_B(c + 1);            // LSU pipe, overlaps MMA

        const uint32_t* aw = smem_u + (c & 3) * 2560 + abase;
        const uint32_t* bw = smem_u + ((c & 1) ? BB1 : BB0) + bidx;

        // k16 step (k_local 0..15)
        {
            uint32_t A[2][4];
            #pragma unroll
            for (int mf = 0; mf < 2; mf++) {
                A[mf][0] = aw[mf * 320];
                A[mf][1] = aw[mf * 320 + 160];
                A[mf][2] = aw[mf * 320 + 4];
                A[mf][3] = aw[mf * 320 + 164];
            }
            #pragma unroll
            for (int nf = 0; nf < 8; nf++) {
                uint32_t B0 = bw[nf * 160];
                uint32_t B1 = bw[nf * 160 + 4];
                mma16(acc[0][nf], A[0], B0, B1);
                mma16(acc[1][nf], A[1], B0, B1);
            }
        }
        // k8 step (k_local 16..23)
        {
            uint32_t A0a = aw[8],       A0b = aw[168];
            uint32_t A1a = aw[320 + 8], A1b = aw[320 + 168];
            #pragma unroll
            for (int nf = 0; nf < 8; nf++) {
                uint32_t B0 = bw[nf * 160 + 8];
                mma8(acc[0][nf], A0a, A0b, B0);
                mma8(acc[1][nf], A1a, A1b, B0);
            }
        }

        if (c + 3 < 16) STAGE(c + 3);   // after MMA: ring reuse behind barrier
    }

    // --- fused BN partial sums
    #pragma unroll
    for (int mf = 0; mf < 2; mf++) {
        float s0 = 0.f, q0 = 0.f, s1 = 0.f, q1 = 0.f;
        #pragma unroll
        for (int nf = 0; nf < 8; nf++) {
            float c0 = acc[mf][nf][0], c1 = acc[mf][nf][1];
            float c2 = acc[mf][nf][2], c3 = acc[mf][nf][3];
            s0 += c0 + c1;  q0 += c0 * c0 + c1 * c1;
            s1 += c2 + c3;  q1 += c2 * c2 + c3 * c3;
        }
        #pragma unroll
        for (int off = 1; off < 4; off <<= 1) {
            s0 += __shfl_xor_sync(0xffffffffu, s0, off);
            q0 += __shfl_xor_sync(0xffffffffu, q0, off);
            s1 += __shfl_xor_sync(0xffffffffu, s1, off);
            q1 += __shfl_xor_sync(0xffffffffu, q1, off);
        }
        if (tig == 0) {
            int co = co0 + m_warp + mf * 16 + g;
            atomicAdd(&g_sum[co],       s0);
            atomicAdd(&g_sqsum[co],     q0);
            atomicAdd(&g_sum[co + 8],   s1);
            atomicAdd(&g_sqsum[co + 8], q1);
        }
    }

    // --- epilogue: two-phase smem transpose, pack to half2, coalesced STG
    float* ys = smem;                      // [64][268]
    #pragma unroll
    for (int ph = 0; ph < 2; ph++) {
        __syncthreads();
        if ((wm >> 1) == ph) {
            #pragma unroll
            for (int mf = 0; mf < 2; mf++)
                #pragma unroll
                for (int nf = 0; nf < 8; nf++) {
                    int row = (wm & 1) * 32 + mf * 16 + g;
                    int nC  = n_warp + nf * 8 + 2 * tig;
                    *(float2*)&ys[row * 268 + nC] =
                        make_float2(acc[mf][nf][0], acc[mf][nf][1]);
                    *(float2*)&ys[(row + 8) * 268 + nC] =
                        make_float2(acc[mf][nf][2], acc[mf][nf][3]);
                }
        }
        __syncthreads();
        int row = t >> 3, jb = t & 7;
        uint32_t* dst = g_yh + ((size_t)(b * 256 + co0 + ph * 64 + row)) * 512 +
                        sgrp * 128;
        #pragma unroll
        for (int jj = 0; jj < 8; jj++) {
            int j = jb + jj * 8;
            float4 v = *(const float4*)&ys[row * 268 + j * 4];
            *(uint2*)&dst[j * 2] = make_uint2(pack_h2(v.x, v.y),
                                              pack_h2(v.z, v.w));
        }
    }
}

// ---------------------------------------------------------------------------
// Normalize + scale/shift + tanh-GELU from half2 scratch; stats inline.
// One thread = 8 values (uint4 of half2).
// ---------------------------------------------------------------------------
__global__ void bn_gelu_kernel(const float* __restrict__ gamma,
                               const float* __restrict__ beta,
                               float* __restrict__ out)
{
    int i = blockIdx.x * 256 + threadIdx.x;    // < 2097152 (uint4 index)
    int co = (i >> 7) & 255;                   // 128 uint4 per (b,co) row
    float mean = g_sum[co] * (1.f / 65536.f);
    float var  = g_sqsum[co] * (1.f / 65536.f) - mean * mean;
    float ga = rsqrtf(var + 1e-5f) * gamma[co];
    float be = beta[co];

    uint4 v = ((const uint4*)g_yh)[i];
    float vals[8];
    {
        float2 f0 = __half22float2(*(__half2*)&v.x);
        float2 f1 = __half22float2(*(__half2*)&v.y);
        float2 f2 = __half22float2(*(__half2*)&v.z);
        float2 f3 = __half22float2(*(__half2*)&v.w);
        vals[0] = f0.x; vals[1] = f0.y; vals[2] = f1.x; vals[3] = f1.y;
        vals[4] = f2.x; vals[5] = f2.y; vals[6] = f3.x; vals[7] = f3.y;
    }
    float r[8];
    #pragma unroll
    for (int j = 0; j < 8; j++) {
        float x = (vals[j] - mean) * ga + be;
        float u = 0.7978845608028654f * (x + 0.044715f * x * x * x);
        r[j] = 0.5f * x * (1.f + tanh_fast(u));
    }
    float4* o = (float4*)&out[(size_t)i * 8];
    o[0] = make_float4(r[0], r[1], r[2], r[3]);
    o[1] = make_float4(r[4], r[5], r[6], r[7]);
}

// ---------------------------------------------------------------------------
extern "C" void kernel_launch(void* const* d_in, const int* in_sizes, int n_in,
                              void* d_out, int out_size)
{
    const float* sparse_fea = (const float*)d_in[0];
    const float* dense_fea  = (const float*)d_in[1];
    const float* stk_coor   = (const float*)d_in[2];
    const float* conv_w     = (const float*)d_in[3];
    // d_in[4] = conv_b: zeros AND cancels under batch-stat BN.
    const float* bn_gamma   = (const float*)d_in[5];
    const float* bn_beta    = (const float*)d_in[6];
    float* out = (float*)d_out;

    cudaFuncSetAttribute(conv_mma_kernel,
                         cudaFuncAttributeMaxDynamicSharedMemorySize, CONV_SMEM);

    wprep_kernel<<<256, 192>>>(conv_w);
    fps_kernel<<<64, 64>>>(stk_coor, out + OFF_COOR);
    gather_sparse<<<2048, 256>>>(sparse_fea, out);
    conv_mma_kernel<<<dim3(8, 64), 512, CONV_SMEM>>>(dense_fea);
    bn_gelu_kernel<<<8192, 256>>>(bn_gamma, bn_beta, out + OFF_DENSE);
}

// round 9
// speedup vs baseline: 1.1929x; 1.0077x over previous
#include <cuda_runtime.h>
#include <cuda_fp16.h>
#include <math.h>
#include <stdint.h>

// ---------------------------------------------------------------------------
// Shapes: sparse_fea[64,256,64] dense_fea[64,128,4096] stk_coor[64,64,32]
//         conv_w[256,128,3] (flat [256][384]) bn_gamma/beta[256]
// Output: sparse_out[64,256,32] | dense_out[64,256,1024] | coor[64,32,32]
// ---------------------------------------------------------------------------

#define OFF_DENSE 524288
#define OFF_COOR  (524288 + 16777216)

__device__ int      g_fps_idx[64 * 32];
__device__ uint32_t g_yh[64 * 256 * 512];     // conv output scratch (half2)
__device__ float    g_sum[256];
__device__ float    g_sqsum[256];
__device__ uint32_t g_wth[256 * 192];         // fp16 weights [co][chunk16][12 half2]

__device__ __forceinline__ unsigned smem_addr(const void* p) {
    return (unsigned)__cvta_generic_to_shared(p);
}
__device__ __forceinline__ void cp_async16(unsigned dst, const void* src) {
    asm volatile("cp.async.cg.shared.global [%0], [%1], 16;\n" :: "r"(dst), "l"(src));
}
__device__ __forceinline__ float tanh_fast(float x) {
    float r;
    asm("tanh.approx.f32 %0, %1;" : "=f"(r) : "f"(x));
    return r;
}
__device__ __forceinline__ void mma16(float c[4], const uint32_t a[4],
                                      uint32_t b0, uint32_t b1) {
    asm volatile(
        "mma.sync.aligned.m16n8k16.row.col.f32.f16.f16.f32 "
        "{%0,%1,%2,%3},{%4,%5,%6,%7},{%8,%9},{%0,%1,%2,%3};"
        : "+f"(c[0]), "+f"(c[1]), "+f"(c[2]), "+f"(c[3])
        : "r"(a[0]), "r"(a[1]), "r"(a[2]), "r"(a[3]), "r"(b0), "r"(b1));
}
__device__ __forceinline__ void mma8(float c[4], uint32_t a0, uint32_t a1,
                                     uint32_t b0) {
    asm volatile(
        "mma.sync.aligned.m16n8k8.row.col.f32.f16.f16.f32 "
        "{%0,%1,%2,%3},{%4,%5},{%6},{%0,%1,%2,%3};"
        : "+f"(c[0]), "+f"(c[1]), "+f"(c[2]), "+f"(c[3])
        : "r"(a0), "r"(a1), "r"(b0));
}
__device__ __forceinline__ uint32_t pack_h2(float lo, float hi) {
    __half2 h = __floats2half2_rn(lo, hi);      // .x = lo (low 16 bits)
    return *(uint32_t*)&h;
}

// ---------------------------------------------------------------------------
// Weight prep: fp16, ordering [co][chunk c][k24], k = cl_local*3 + tap,
// packed as 12 half2 words per (co, chunk).
// ---------------------------------------------------------------------------
__global__ void wprep_kernel(const float* __restrict__ w)
{
    int co = blockIdx.x;                 // 256
    int t  = threadIdx.x;                // 0..191
    int c  = t / 12;
    int j  = t - c * 12;                 // half2 index
    int k0 = 2 * j, k1 = 2 * j + 1;
    int cin0 = c * 8 + k0 / 3, tap0 = k0 % 3;
    int cin1 = c * 8 + k1 / 3, tap1 = k1 % 3;
    float f0 = w[co * 384 + cin0 * 3 + tap0];
    float f1 = w[co * 384 + cin1 * 3 + tap1];
    g_wth[co * 192 + c * 12 + j] = pack_h2(f0, f1);
}

// ---------------------------------------------------------------------------
// FPS: one block per batch, 64 threads. Block 0 zeroes BN accumulators.
// ---------------------------------------------------------------------------
__global__ void fps_kernel(const float* __restrict__ stk_coor,
                           float* __restrict__ out_coor)
{
    int b = blockIdx.x;
    int t = threadIdx.x;                     // 0..63

    if (b == 0) {
        for (int i = t; i < 256; i += 64) { g_sum[i] = 0.f; g_sqsum[i] = 0.f; }
    }

    __shared__ float coor[64][33];
    __shared__ float sdist[64];
    __shared__ int   sidx[32];
    __shared__ int   s_far;

    #pragma unroll
    for (int c = 0; c < 32; c++)
        coor[t][c] = stk_coor[(b * 64 + t) * 32 + c];
    if (t == 0) s_far = 0;
    float dist = 1e10f;
    __syncthreads();

    for (int i = 0; i < 32; i++) {
        int far = s_far;
        if (t == 0) sidx[i] = far;
        float d = 0.f;
        #pragma unroll
        for (int c = 0; c < 32; c++) {
            float df = coor[t][c] - coor[far][c];
            d += df * df;
        }
        dist = fminf(dist, d);
        sdist[t] = dist;
        __syncthreads();
        if (t < 32) {
            float bv = sdist[t];       int bi = t;
            float v2 = sdist[t + 32];
            if (v2 > bv) { bv = v2; bi = t + 32; }
            #pragma unroll
            for (int off = 16; off > 0; off >>= 1) {
                float ov = __shfl_down_sync(0xffffffffu, bv, off);
                int   oi = __shfl_down_sync(0xffffffffu, bi, off);
                if (ov > bv || (ov == bv && oi < bi)) { bv = ov; bi = oi; }
            }
            if (t == 0) s_far = bi;
        }
        __syncthreads();
    }

    if (t < 32) g_fps_idx[b * 32 + t] = sidx[t];
    for (int v = t; v < 32 * 32; v += 64) {
        int i = v >> 5, c = v & 31;
        out_coor[(b * 32 + i) * 32 + c] = coor[sidx[i]][c];
    }
}

// ---------------------------------------------------------------------------
// sparse_out[b,e,s] = sparse_fea[b,e,idx[b,s]]
// ---------------------------------------------------------------------------
__global__ void gather_sparse(const float* __restrict__ sp,
                              float* __restrict__ out)
{
    int t = blockIdx.x * 256 + threadIdx.x;     // < 524288
    int b = t >> 13;
    int r = t & 8191;
    int e = r >> 5;
    int s = r & 31;
    out[t] = sp[(size_t)(b * 256 + e) * 64 + g_fps_idx[b * 32 + s]];
}

// ---------------------------------------------------------------------------
// fp16 conv-as-GEMM, cp.async 3-deep pipeline, ONE barrier per K-chunk.
// 512 threads, tile M=128 co x N=256 (8 strokes x 32 q), K=384 in 16x24.
// smem word offsets (ring buffers):
//   WB(i)  = i*2560,        i=0..3 : fp16 weights [128 co][20w, 12 used]
//   BB0 10240, BB1 15360           : im2col B [256 n][20w, 12 used]
//   RAW(i) = 20480 + i*4608, i=0..3: raw x rows [64][72], x[p]@p+4, 0@3
// Iter c: wait_group 1; bar; BUILD_B(c+1) || MMA(c); stage(c+3).
// Ring reuse is always separated by >=1 barrier (audited per buffer).
// Epilogue reuses smem as ys[64][268]; y stored to gmem as half2.
// ---------------------------------------------------------------------------
#define BB0  10240
#define BB1  15360
#define RAWB 20480
#define CONV_SMEM 155648

__global__ void __launch_bounds__(512, 1)
conv_mma_kernel(const float* __restrict__ dense)
{
    extern __shared__ float smem[];
    uint32_t* smem_u = (uint32_t*)smem;

    const int b    = blockIdx.y;
    const int ch   = blockIdx.x & 1;       // co half
    const int sgrp = blockIdx.x >> 1;      // 0..3
    const int co0  = ch * 128;
    const int t    = threadIdx.x;
    const int wp   = t >> 5;               // 0..15
    const int lane = t & 31;
    const int g    = lane >> 2;
    const int tig  = lane & 3;
    const int wm   = wp & 3;
    const int wn   = wp >> 2;
    const int m_warp = wm * 32;
    const int n_warp = wn * 64;

    __shared__ int stk[8];
    if (t < 8) stk[t] = g_fps_idx[b * 32 + sgrp * 8 + t];
    if (t < 256) {                         // zero p=-1 pads in all 4 RAW bufs
        int bi = t >> 6, r = t & 63;
        smem[RAWB + bi * 4608 + r * 72 + 3] = 0.f;
    }
    __syncthreads();

    // one commit group per chunk: x rows (cp.async direct to RAW) + weights
    #define STAGE(cc)                                                        \
        {                                                                    \
            int rb = (cc) & 3;                                               \
            _Pragma("unroll")                                                \
            for (int i = 0; i < 2; i++) {                                    \
                int v = t + 512 * i;                                         \
                int row = v >> 4, j = v & 15;                                \
                int cl = row >> 3, s = row & 7;                              \
                cp_async16(smem_addr(smem_u + RAWB + rb * 4608 +             \
                                     row * 72 + 4 + 4 * j),                  \
                           &dense[(size_t)(b * 128 + (cc) * 8 + cl) * 4096 + \
                                  (size_t)stk[s] * 64 + j * 4]);             \
            }                                                                \
            if (t < 384) {                                                   \
                int co = t / 3, seg = t - co * 3;                            \
                cp_async16(smem_addr(smem_u + rb * 2560 + co * 20 + seg * 4),\
                           g_wth + (size_t)(co0 + co) * 192 + (cc) * 12 +    \
                           seg * 4);                                         \
            }                                                                \
            asm volatile("cp.async.commit_group;");                          \
        }

    // im2col build: thread covers n = t&255, k-half h2 = t>>8 (6 half2 each)
    #define BUILD_B(cc)                                                      \
        {                                                                    \
            int n  = t & 255;                                                \
            int h2 = t >> 8;                                                 \
            int s  = n >> 5, q = n & 31;                                     \
            const float* rbase = smem + RAWB + ((cc) & 3) * 4608;            \
            float f[12];                                                     \
            _Pragma("unroll")                                                \
            for (int cr = 0; cr < 4; cr++) {                                 \
                const float* rrow = rbase + (h2 * 4 + cr) * 576 +            \
                                    s * 72 + 2 * q;                          \
                float2 u0 = *(const float2*)(rrow + 2);                      \
                float2 u1 = *(const float2*)(rrow + 4);                      \
                f[cr * 3 + 0] = u0.y;                                        \
                f[cr * 3 + 1] = u1.x;                                        \
                f[cr * 3 + 2] = u1.y;                                        \
            }                                                                \
            uint32_t* dst = smem_u + (((cc) & 1) ? BB1 : BB0) + n * 20 +     \
                            h2 * 6;                                          \
            ((uint2*)dst)[0] = make_uint2(pack_h2(f[0], f[1]),               \
                                          pack_h2(f[2], f[3]));              \
            ((uint2*)(dst + 2))[0] = make_uint2(pack_h2(f[4], f[5]),         \
                                                pack_h2(f[6], f[7]));        \
            ((uint2*)(dst + 4))[0] = make_uint2(pack_h2(f[8], f[9]),         \
                                                pack_h2(f[10], f[11]));      \
        }

    // prologue: fill pipeline with chunks 0,1,2
    STAGE(0);
    STAGE(1);
    STAGE(2);
    asm volatile("cp.async.wait_group 2;");    // chunk 0 arrived
    __syncthreads();
    BUILD_B(0);

    // fragment base offsets (word units)
    const int abase = m_warp * 20 + g * 20 + tig;          // + wbuf*2560
    const int bidx  = (n_warp + g) * 20 + tig;             // + BBx + nf*160

    float acc[2][8][4];
    #pragma unroll
    for (int mf = 0; mf < 2; mf++)
        #pragma unroll
        for (int nf = 0; nf < 8; nf++)
            #pragma unroll
            for (int i = 0; i < 4; i++) acc[mf][nf][i] = 0.f;

    for (int c = 0; c < 16; ++c) {
        asm volatile("cp.async.wait_group 1;");    // chunk c+1 arrived
        __syncthreads();    // publishes BUILD_B(c) + RAW(c+1); retires MMA(c-1)

        if (c + 1 < 16) BUILD_B(c + 1);            // LSU pipe, overlaps MMA

        const uint32_t* aw = smem_u + (c & 3) * 2560 + abase;
        const uint32_t* bw = smem_u + ((c & 1) ? BB1 : BB0) + bidx;

        // k16 step (k_local 0..15)
        {
            uint32_t A[2][4];
            #pragma unroll
            for (int mf = 0; mf < 2; mf++) {
                A[mf][0] = aw[mf * 320];
                A[mf][1] = aw[mf * 320 + 160];
                A[mf][2] = aw[mf * 320 + 4];
                A[mf][3] = aw[mf * 320 + 164];
            }
            #pragma unroll
            for (int nf = 0; nf < 8; nf++) {
                uint32_t B0 = bw[nf * 160];
                uint32_t B1 = bw[nf * 160 + 4];
                mma16(acc[0][nf], A[0], B0, B1);
                mma16(acc[1][nf], A[1], B0, B1);
            }
        }
        // k8 step (k_local 16..23)
        {
            uint32_t A0a = aw[8],       A0b = aw[168];
            uint32_t A1a = aw[320 + 8], A1b = aw[320 + 168];
            #pragma unroll
            for (int nf = 0; nf < 8; nf++) {
                uint32_t B0 = bw[nf * 160 + 8];
                mma8(acc[0][nf], A0a, A0b, B0);
                mma8(acc[1][nf], A1a, A1b, B0);
            }
        }

        if (c + 3 < 16) STAGE(c + 3);   // after MMA: ring reuse behind barrier
    }

    // --- fused BN partial sums
    #pragma unroll
    for (int mf = 0; mf < 2; mf++) {
        float s0 = 0.f, q0 = 0.f, s1 = 0.f, q1 = 0.f;
        #pragma unroll
        for (int nf = 0; nf < 8; nf++) {
            float c0 = acc[mf][nf][0], c1 = acc[mf][nf][1];
            float c2 = acc[mf][nf][2], c3 = acc[mf][nf][3];
            s0 += c0 + c1;  q0 += c0 * c0 + c1 * c1;
            s1 += c2 + c3;  q1 += c2 * c2 + c3 * c3;
        }
        #pragma unroll
        for (int off = 1; off < 4; off <<= 1) {
            s0 += __shfl_xor_sync(0xffffffffu, s0, off);
            q0 += __shfl_xor_sync(0xffffffffu, q0, off);
            s1 += __shfl_xor_sync(0xffffffffu, s1, off);
            q1 += __shfl_xor_sync(0xffffffffu, q1, off);
        }
        if (tig == 0) {
            int co = co0 + m_warp + mf * 16 + g;
            atomicAdd(&g_sum[co],       s0);
            atomicAdd(&g_sqsum[co],     q0);
            atomicAdd(&g_sum[co + 8],   s1);
            atomicAdd(&g_sqsum[co + 8], q1);
        }
    }

    // --- epilogue: two-phase smem transpose, pack to half2, coalesced STG
    float* ys = smem;                      // [64][268]
    #pragma unroll
    for (int ph = 0; ph < 2; ph++) {
        __syncthreads();
        if ((wm >> 1) == ph) {
            #pragma unroll
            for (int mf = 0; mf < 2; mf++)
                #pragma unroll
                for (int nf = 0; nf < 8; nf++) {
                    int row = (wm & 1) * 32 + mf * 16 + g;
                    int nC  = n_warp + nf * 8 + 2 * tig;
                    *(float2*)&ys[row * 268 + nC] =
                        make_float2(acc[mf][nf][0], acc[mf][nf][1]);
                    *(float2*)&ys[(row + 8) * 268 + nC] =
                        make_float2(acc[mf][nf][2], acc[mf][nf][3]);
                }
        }
        __syncthreads();
        int row = t >> 3, jb = t & 7;
        uint32_t* dst = g_yh + ((size_t)(b * 256 + co0 + ph * 64 + row)) * 512 +
                        sgrp * 128;
        #pragma unroll
        for (int jj = 0; jj < 8; jj++) {
            int j = jb + jj * 8;
            float4 v = *(const float4*)&ys[row * 268 + j * 4];
            *(uint2*)&dst[j * 2] = make_uint2(pack_h2(v.x, v.y),
                                              pack_h2(v.z, v.w));
        }
    }
}

// ---------------------------------------------------------------------------
// Normalize + scale/shift + tanh-GELU from half2 scratch; stats inline.
// One thread = 8 values (uint4 of half2).
// ---------------------------------------------------------------------------
__global__ void bn_gelu_kernel(const float* __restrict__ gamma,
                               const float* __restrict__ beta,
                               float* __restrict__ out)
{
    int i = blockIdx.x * 256 + threadIdx.x;    // < 2097152 (uint4 index)
    int co = (i >> 7) & 255;                   // 128 uint4 per (b,co) row
    float mean = g_sum[co] * (1.f / 65536.f);
    float var  = g_sqsum[co] * (1.f / 65536.f) - mean * mean;
    float ga = rsqrtf(var + 1e-5f) * gamma[co];
    float be = beta[co];

    uint4 v = ((const uint4*)g_yh)[i];
    float vals[8];
    {
        float2 f0 = __half22float2(*(__half2*)&v.x);
        float2 f1 = __half22float2(*(__half2*)&v.y);
        float2 f2 = __half22float2(*(__half2*)&v.z);
        float2 f3 = __half22float2(*(__half2*)&v.w);
        vals[0] = f0.x; vals[1] = f0.y; vals[2] = f1.x; vals[3] = f1.y;
        vals[4] = f2.x; vals[5] = f2.y; vals[6] = f3.x; vals[7] = f3.y;
    }
    float r[8];
    #pragma unroll
    for (int j = 0; j < 8; j++) {
        float x = (vals[j] - mean) * ga + be;
        float u = 0.7978845608028654f * (x + 0.044715f * x * x * x);
        r[j] = 0.5f * x * (1.f + tanh_fast(u));
    }
    float4* o = (float4*)&out[(size_t)i * 8];
    o[0] = make_float4(r[0], r[1], r[2], r[3]);
    o[1] = make_float4(r[4], r[5], r[6], r[7]);
}

// ---------------------------------------------------------------------------
extern "C" void kernel_launch(void* const* d_in, const int* in_sizes, int n_in,
                              void* d_out, int out_size)
{
    const float* sparse_fea = (const float*)d_in[0];
    const float* dense_fea  = (const float*)d_in[1];
    const float* stk_coor   = (const float*)d_in[2];
    const float* conv_w     = (const float*)d_in[3];
    // d_in[4] = conv_b: zeros AND cancels under batch-stat BN.
    const float* bn_gamma   = (const float*)d_in[5];
    const float* bn_beta    = (const float*)d_in[6];
    float* out = (float*)d_out;

    cudaFuncSetAttribute(conv_mma_kernel,
                         cudaFuncAttributeMaxDynamicSharedMemorySize, CONV_SMEM);

    wprep_kernel<<<256, 192>>>(conv_w);
    fps_kernel<<<64, 64>>>(stk_coor, out + OFF_COOR);
    gather_sparse<<<2048, 256>>>(sparse_fea, out);
    conv_mma_kernel<<<dim3(8, 64), 512, CONV_SMEM>>>(dense_fea);
    bn_gelu_kernel<<<8192, 256>>>(bn_gamma, bn_beta, out + OFF_DENSE);
}